// round 12
// baseline (speedup 1.0000x reference)
#include <cuda_runtime.h>
#include <cstdint>

#define N_NODES 50000
#define N_EDGES 600000
#define D 128
#define EPS 1e-5f

// ---------------- scratch (static device globals; no allocation) -------------
// NEVER passed as kernel arguments from host (host sees only the shadow var;
// GB300 ATS makes that a silent host-memory write). Referenced in device code.
__device__ __align__(16) float g_xw[(size_t)N_NODES * D];   // x @ W^T
__device__ __align__(16) float g_agg[(size_t)N_NODES * D];  // aggregated output
__device__ int   g_degi[N_NODES];
__device__ float g_dinv[N_NODES];
__device__ int   g_off[N_NODES + 1];   // CSR row offsets (by target node)
__device__ int   g_cur[N_NODES];       // fill cursors
__device__ int   g_src[N_EDGES];       // CSR column data: source node ids
__device__ float g_colsum[D];
__device__ float g_colss[D];
__device__ float g_mean[D];
__device__ float g_scale;
__device__ int   g_is64;

// ---------------- edge dtype helper (int64 vs int32 storage) -----------------
__device__ __forceinline__ int edge_at(const void* ei, int idx) {
    int v;
    if (g_is64) v = (int)__ldg(&((const long long*)ei)[idx]);
    else        v = __ldg(&((const int*)ei)[idx]);
    return (v < 0) ? 0 : (v >= N_NODES ? N_NODES - 1 : v);  // never fault
}

// ---------------- zero small scratch + dtype sniff ----------------------------
__global__ void k_zero(const int* __restrict__ ei32) {
    int idx = blockIdx.x * blockDim.x + threadIdx.x;
    int stride = gridDim.x * blockDim.x;
    if (idx == 0) {
        int all_zero = 1;
        for (int i = 0; i < 256; i++)
            if (__ldg(&ei32[2 * i + 1]) != 0) { all_zero = 0; break; }
        g_is64 = all_zero;
    }
    for (int i = idx; i < N_NODES; i += stride) g_degi[i] = 0;
    if (idx < D) { g_colsum[idx] = 0.f; g_colss[idx] = 0.f; }
}

// ---------------- in-degree histogram (int) ----------------------------------
__global__ void k_degree(const void* __restrict__ ei) {
    int e = blockIdx.x * blockDim.x + threadIdx.x;
    if (e < N_EDGES) atomicAdd(&g_degi[edge_at(ei, N_EDGES + e)], 1);
}

// ---------------- one-block exclusive scan + dinv + cursor init ---------------
#define SCAN_T 1024
__global__ __launch_bounds__(SCAN_T) void k_scan() {
    __shared__ int ssum[SCAN_T];
    const int t = threadIdx.x;
    const int CH = (N_NODES + SCAN_T - 1) / SCAN_T;  // 49
    const int base = t * CH;
    int local = 0;
    for (int i = 0; i < CH; i++) {
        int n = base + i;
        if (n < N_NODES) local += g_degi[n];
    }
    ssum[t] = local;
    __syncthreads();
    for (int off = 1; off < SCAN_T; off <<= 1) {     // Hillis-Steele inclusive
        int v = (t >= off) ? ssum[t - off] : 0;
        __syncthreads();
        ssum[t] += v;
        __syncthreads();
    }
    int start = ssum[t] - local;                     // exclusive prefix
    for (int i = 0; i < CH; i++) {
        int n = base + i;
        if (n < N_NODES) {
            g_off[n] = start;
            g_cur[n] = start;
            int d = g_degi[n];
            g_dinv[n] = rsqrtf((float)d + 1.0f);     // +1 self loop
            start += d;
        }
    }
    if (t == SCAN_T - 1) g_off[N_NODES] = ssum[SCAN_T - 1];
}

// ---------------- CSR fill (cheap int atomics) --------------------------------
__global__ void k_fill(const void* __restrict__ ei) {
    int e = blockIdx.x * blockDim.x + threadIdx.x;
    if (e < N_EDGES) {
        int r = edge_at(ei, e);              // source
        int c = edge_at(ei, N_EDGES + e);    // target
        int pos = atomicAdd(&g_cur[c], 1);
        g_src[pos] = r;
    }
}

// ---------------- GEMM: g_xw = x @ W^T  (FFMA2-packed fp32) -------------------
#define GM 128
#define GN 64
#define GK 32
#define SA_STRIDE (GM + 2)   // 130 floats = 520B: 8B-aligned rows, 2-way store conflicts only
#define SB_STRIDE (GN + 4)   // 68 floats = 272B: 16B-aligned rows
__global__ __launch_bounds__(256) void k_gemm(const float* __restrict__ A,
                                              const float* __restrict__ Wm) {
    __shared__ float sA[GK][SA_STRIDE];
    __shared__ float sB[GK][SB_STRIDE];
    const int tid = threadIdx.x;
    const int brow = blockIdx.x * GM;
    const int bcol = blockIdx.y * GN;
    const int tx = tid & 15;   // cols tx*4 .. +3
    const int ty = tid >> 4;   // rows ty*8 .. +7

    unsigned long long acc2[4][4];   // [i-pair][j], lo = row 2*i2, hi = row 2*i2+1
#pragma unroll
    for (int i2 = 0; i2 < 4; i2++)
#pragma unroll
        for (int j = 0; j < 4; j++) acc2[i2][j] = 0ULL;

    for (int k0 = 0; k0 < D; k0 += GK) {
#pragma unroll
        for (int p = 0; p < 4; p++) {            // A tile: 128 x 32 (transposed)
            int r  = (tid >> 3) + p * 32;
            int kk = (tid & 7) * 4;
            int gr = brow + r;
            float4 v = make_float4(0.f, 0.f, 0.f, 0.f);
            if (gr < N_NODES)
                v = *reinterpret_cast<const float4*>(A + (size_t)gr * D + k0 + kk);
            sA[kk + 0][r] = v.x; sA[kk + 1][r] = v.y;
            sA[kk + 2][r] = v.z; sA[kk + 3][r] = v.w;
        }
#pragma unroll
        for (int p = 0; p < 2; p++) {            // B tile: 64 x 32 (transposed)
            int r  = (tid >> 3) + p * 32;
            int kk = (tid & 7) * 4;
            float4 v = *reinterpret_cast<const float4*>(Wm + (size_t)(bcol + r) * D + k0 + kk);
            sB[kk + 0][r] = v.x; sB[kk + 1][r] = v.y;
            sB[kk + 2][r] = v.z; sB[kk + 3][r] = v.w;
        }
        __syncthreads();

#pragma unroll
        for (int kk = 0; kk < GK; kk++) {
            unsigned long long a2[4];            // row pairs (2*i2, 2*i2+1)
            const float* arow = &sA[kk][ty * 8];
#pragma unroll
            for (int q = 0; q < 4; q++)
                a2[q] = *reinterpret_cast<const unsigned long long*>(arow + 2 * q);

            float4 b4 = *reinterpret_cast<const float4*>(&sB[kk][tx * 4]);
            unsigned long long bb[4];
            asm("mov.b64 %0, {%1, %1};" : "=l"(bb[0]) : "f"(b4.x));
            asm("mov.b64 %0, {%1, %1};" : "=l"(bb[1]) : "f"(b4.y));
            asm("mov.b64 %0, {%1, %1};" : "=l"(bb[2]) : "f"(b4.z));
            asm("mov.b64 %0, {%1, %1};" : "=l"(bb[3]) : "f"(b4.w));

#pragma unroll
            for (int i2 = 0; i2 < 4; i2++)
#pragma unroll
                for (int j = 0; j < 4; j++)
                    asm("fma.rn.f32x2 %0, %1, %2, %0;"
                        : "+l"(acc2[i2][j]) : "l"(a2[i2]), "l"(bb[j]));
        }
        __syncthreads();
    }

#pragma unroll
    for (int i2 = 0; i2 < 4; i2++) {
        float lo[4], hi[4];
#pragma unroll
        for (int j = 0; j < 4; j++)
            asm("mov.b64 {%0, %1}, %2;" : "=f"(lo[j]), "=f"(hi[j]) : "l"(acc2[i2][j]));
        int gr = brow + ty * 8 + 2 * i2;
        if (gr < N_NODES)
            *reinterpret_cast<float4*>(g_xw + (size_t)gr * D + bcol + tx * 4) =
                make_float4(lo[0], lo[1], lo[2], lo[3]);
        if (gr + 1 < N_NODES)
            *reinterpret_cast<float4*>(g_xw + (size_t)(gr + 1) * D + bcol + tx * 4) =
                make_float4(hi[0], hi[1], hi[2], hi[3]);
    }
}

// ---------------- pull aggregate (warp per node) + fused column stats ---------
__global__ __launch_bounds__(256) void k_agg() {
    const int lane = threadIdx.x & 31;
    const int warp0 = (blockIdx.x * blockDim.x + threadIdx.x) >> 5;
    const int nwarps = gridDim.x * (blockDim.x >> 5);

    float s[4]  = {0.f, 0.f, 0.f, 0.f};   // per-lane column sums (cols lane*4+q)
    float ss[4] = {0.f, 0.f, 0.f, 0.f};   // per-lane column sumsq

    for (int v = warp0; v < N_NODES; v += nwarps) {
        float dv = g_dinv[v];
        float4 acc = reinterpret_cast<const float4*>(g_xw + (size_t)v * D)[lane];
        acc.x *= dv; acc.y *= dv; acc.z *= dv; acc.w *= dv;   // self loop inner

        int e0 = g_off[v], e1 = g_off[v + 1];
        for (int e = e0; e < e1; e++) {
            int u = g_src[e];                                  // warp-broadcast
            float du = g_dinv[u];
            float4 xu = reinterpret_cast<const float4*>(g_xw + (size_t)u * D)[lane];
            acc.x = fmaf(du, xu.x, acc.x);
            acc.y = fmaf(du, xu.y, acc.y);
            acc.z = fmaf(du, xu.z, acc.z);
            acc.w = fmaf(du, xu.w, acc.w);
        }
        acc.x *= dv; acc.y *= dv; acc.z *= dv; acc.w *= dv;   // outer dinv[v]
        reinterpret_cast<float4*>(g_agg + (size_t)v * D)[lane] = acc;

        s[0] += acc.x; s[1] += acc.y; s[2] += acc.z; s[3] += acc.w;
        ss[0] += acc.x * acc.x; ss[1] += acc.y * acc.y;
        ss[2] += acc.z * acc.z; ss[3] += acc.w * acc.w;
    }

    // block-level stats reduction, then 256 global atomics per block
    __shared__ float sm_s[D], sm_ss[D];
    if (threadIdx.x < D) { sm_s[threadIdx.x] = 0.f; sm_ss[threadIdx.x] = 0.f; }
    __syncthreads();
#pragma unroll
    for (int q = 0; q < 4; q++) {
        atomicAdd(&sm_s[lane * 4 + q], s[q]);     // distinct banks within warp
        atomicAdd(&sm_ss[lane * 4 + q], ss[q]);
    }
    __syncthreads();
    if (threadIdx.x < D) {
        atomicAdd(&g_colsum[threadIdx.x], sm_s[threadIdx.x]);
        atomicAdd(&g_colss[threadIdx.x],  sm_ss[threadIdx.x]);
    }
}

// ---------------- finalize PairNorm stats -------------------------------------
__global__ __launch_bounds__(D) void k_finalize_stats() {
    const int c = threadIdx.x;
    float m = g_colsum[c] * (1.0f / N_NODES);
    g_mean[c] = m;
    float ssc = g_colss[c] - (float)N_NODES * m * m;  // sum (v-m)^2
    __shared__ float red[D];
    red[c] = ssc;
    __syncthreads();
    for (int off = D / 2; off > 0; off >>= 1) {
        if (c < off) red[c] += red[c + off];
        __syncthreads();
    }
    if (c == 0) g_scale = rsqrtf(EPS + red[0] * (1.0f / N_NODES));
}

// ---------------- normalize + relu + residual ---------------------------------
__global__ void k_output(float* __restrict__ out) {
    const int idx = blockIdx.x * blockDim.x + threadIdx.x;
    const int n4 = N_NODES * D / 4;
    if (idx >= n4) return;
    const int c = (idx & (D / 4 - 1)) * 4;
    const float scale = g_scale;
    float4 v = reinterpret_cast<const float4*>(g_agg)[idx];
    float o0 = (v.x - g_mean[c + 0]) * scale;
    float o1 = (v.y - g_mean[c + 1]) * scale;
    float o2 = (v.z - g_mean[c + 2]) * scale;
    float o3 = (v.w - g_mean[c + 3]) * scale;
    float4 y;
    y.x = fmaxf(o0, 0.f) + o0;
    y.y = fmaxf(o1, 0.f) + o1;
    y.z = fmaxf(o2, 0.f) + o2;
    y.w = fmaxf(o3, 0.f) + o3;
    reinterpret_cast<float4*>(out)[idx] = y;
}

// ---------------- launch -------------------------------------------------------
extern "C" void kernel_launch(void* const* d_in, const int* in_sizes, int n_in,
                              void* d_out, int out_size) {
    // identify inputs by element count, not position
    const float* x  = nullptr;
    const float* Wm = nullptr;
    const void*  ei = nullptr;
    for (int i = 0; i < n_in; i++) {
        if (in_sizes[i] == N_NODES * D)           x  = (const float*)d_in[i];
        else if (in_sizes[i] == D * D)            Wm = (const float*)d_in[i];
        else if (in_sizes[i] == 2 * N_EDGES ||
                 in_sizes[i] == 4 * N_EDGES)      ei = d_in[i];
    }
    if (!x)  x  = (const float*)d_in[0];
    if (!Wm) Wm = (const float*)d_in[1];
    if (!ei) ei = d_in[2];
    float* out = (float*)d_out;

    k_zero<<<196, 256>>>((const int*)ei);
    k_degree<<<(N_EDGES + 255) / 256, 256>>>(ei);
    k_scan<<<1, SCAN_T>>>();
    k_fill<<<(N_EDGES + 255) / 256, 256>>>(ei);

    dim3 ggrid((N_NODES + GM - 1) / GM, D / GN);
    k_gemm<<<ggrid, 256>>>(x, Wm);

    k_agg<<<1184, 256>>>();
    k_finalize_stats<<<1, D>>>();

    const int n4 = N_NODES * D / 4;
    k_output<<<(n4 + 255) / 256, 256>>>(out);
}

// round 13
// speedup vs baseline: 1.1857x; 1.1857x over previous
#include <cuda_runtime.h>
#include <cstdint>

#define N_NODES 50000
#define N_EDGES 600000
#define D 128
#define EPS 1e-5f

// ---------------- scratch (static device globals; no allocation) -------------
// NEVER passed as kernel arguments from host (host sees only the shadow var;
// GB300 ATS makes that a silent host-memory write). Referenced in device code.
__device__ __align__(16) float g_xw[(size_t)N_NODES * D];   // x @ W^T
__device__ __align__(16) float g_agg[(size_t)N_NODES * D];  // scatter accumulator
__device__ float g_deg[N_NODES];
__device__ float g_dinv[N_NODES];
__device__ float g_colsum[D];
__device__ float g_colss[D];
__device__ float g_mean[D];
__device__ float g_scale;
__device__ int   g_is64;

// ---------------- edge dtype helper (int64 vs int32 storage) -----------------
__device__ __forceinline__ int edge_at(const void* ei, int idx) {
    int v;
    if (g_is64) v = (int)__ldg(&((const long long*)ei)[idx]);
    else        v = __ldg(&((const int*)ei)[idx]);
    return (v < 0) ? 0 : (v >= N_NODES ? N_NODES - 1 : v);  // never fault
}

// ---------------- zero scratch + dtype sniff (graph-replay safe) -------------
__global__ void k_zero(const int* __restrict__ ei32) {
    int idx = blockIdx.x * blockDim.x + threadIdx.x;
    int stride = gridDim.x * blockDim.x;
    if (idx == 0) {
        int all_zero = 1;
        for (int i = 0; i < 256; i++)
            if (__ldg(&ei32[2 * i + 1]) != 0) { all_zero = 0; break; }
        g_is64 = all_zero;
    }
    float4 z = make_float4(0.f, 0.f, 0.f, 0.f);
    float4* agg4 = reinterpret_cast<float4*>(g_agg);
    const int n4 = N_NODES * D / 4;
    for (int i = idx; i < n4; i += stride) agg4[i] = z;
    for (int i = idx; i < N_NODES; i += stride) g_deg[i] = 0.f;
    if (idx < D) { g_colsum[idx] = 0.f; g_colss[idx] = 0.f; }
}

// ---------------- degree count ----------------------------------------------
__global__ void k_degree(const void* __restrict__ ei) {
    int e = blockIdx.x * blockDim.x + threadIdx.x;
    if (e < N_EDGES) atomicAdd(&g_deg[edge_at(ei, N_EDGES + e)], 1.0f);
}

__global__ void k_dinv() {
    int i = blockIdx.x * blockDim.x + threadIdx.x;
    if (i < N_NODES) g_dinv[i] = rsqrtf(g_deg[i] + 1.0f);  // +1 self loop
}

// ---------------- GEMM: g_xw = x @ W^T  (FFMA2-packed fp32) -------------------
// Validated bit-exact in R11. Inner loop ~29 issue slots/kk vs 44 scalar.
#define GM 128
#define GN 64
#define GK 32
#define SA_STRIDE (GM + 2)   // 130 floats: 8B-aligned rows for LDS.64 a-pairs
#define SB_STRIDE (GN + 4)   // 68 floats: 16B-aligned rows for LDS.128 b
__global__ __launch_bounds__(256) void k_gemm(const float* __restrict__ A,
                                              const float* __restrict__ Wm) {
    __shared__ float sA[GK][SA_STRIDE];
    __shared__ float sB[GK][SB_STRIDE];
    const int tid = threadIdx.x;
    const int brow = blockIdx.x * GM;
    const int bcol = blockIdx.y * GN;
    const int tx = tid & 15;   // cols tx*4 .. +3
    const int ty = tid >> 4;   // rows ty*8 .. +7

    unsigned long long acc2[4][4];   // [row-pair][col]: lo=row 2*i2, hi=row 2*i2+1
#pragma unroll
    for (int i2 = 0; i2 < 4; i2++)
#pragma unroll
        for (int j = 0; j < 4; j++) acc2[i2][j] = 0ULL;

    for (int k0 = 0; k0 < D; k0 += GK) {
#pragma unroll
        for (int p = 0; p < 4; p++) {            // A tile: 128 x 32 (transposed)
            int r  = (tid >> 3) + p * 32;
            int kk = (tid & 7) * 4;
            int gr = brow + r;
            float4 v = make_float4(0.f, 0.f, 0.f, 0.f);
            if (gr < N_NODES)
                v = *reinterpret_cast<const float4*>(A + (size_t)gr * D + k0 + kk);
            sA[kk + 0][r] = v.x; sA[kk + 1][r] = v.y;
            sA[kk + 2][r] = v.z; sA[kk + 3][r] = v.w;
        }
#pragma unroll
        for (int p = 0; p < 2; p++) {            // B tile: 64 x 32 (transposed)
            int r  = (tid >> 3) + p * 32;
            int kk = (tid & 7) * 4;
            float4 v = *reinterpret_cast<const float4*>(Wm + (size_t)(bcol + r) * D + k0 + kk);
            sB[kk + 0][r] = v.x; sB[kk + 1][r] = v.y;
            sB[kk + 2][r] = v.z; sB[kk + 3][r] = v.w;
        }
        __syncthreads();

#pragma unroll
        for (int kk = 0; kk < GK; kk++) {
            unsigned long long a2[4];
            const float* arow = &sA[kk][ty * 8];
#pragma unroll
            for (int q = 0; q < 4; q++)
                a2[q] = *reinterpret_cast<const unsigned long long*>(arow + 2 * q);

            float4 b4 = *reinterpret_cast<const float4*>(&sB[kk][tx * 4]);
            unsigned long long bb[4];
            asm("mov.b64 %0, {%1, %1};" : "=l"(bb[0]) : "f"(b4.x));
            asm("mov.b64 %0, {%1, %1};" : "=l"(bb[1]) : "f"(b4.y));
            asm("mov.b64 %0, {%1, %1};" : "=l"(bb[2]) : "f"(b4.z));
            asm("mov.b64 %0, {%1, %1};" : "=l"(bb[3]) : "f"(b4.w));

#pragma unroll
            for (int i2 = 0; i2 < 4; i2++)
#pragma unroll
                for (int j = 0; j < 4; j++)
                    asm("fma.rn.f32x2 %0, %1, %2, %0;"
                        : "+l"(acc2[i2][j]) : "l"(a2[i2]), "l"(bb[j]));
        }
        __syncthreads();
    }

#pragma unroll
    for (int i2 = 0; i2 < 4; i2++) {
        float lo[4], hi[4];
#pragma unroll
        for (int j = 0; j < 4; j++)
            asm("mov.b64 {%0, %1}, %2;" : "=f"(lo[j]), "=f"(hi[j]) : "l"(acc2[i2][j]));
        int gr = brow + ty * 8 + 2 * i2;
        if (gr < N_NODES)
            *reinterpret_cast<float4*>(g_xw + (size_t)gr * D + bcol + tx * 4) =
                make_float4(lo[0], lo[1], lo[2], lo[3]);
        if (gr + 1 < N_NODES)
            *reinterpret_cast<float4*>(g_xw + (size_t)(gr + 1) * D + bcol + tx * 4) =
                make_float4(hi[0], hi[1], hi[2], hi[3]);
    }
}

// ---------------- gather + scale + scatter-add (warp per edge) ---------------
// R10-measured path (~100us in the 184.4us total). Write-heavy but latency-flat.
__global__ __launch_bounds__(256) void k_scatter(const void* __restrict__ ei) {
    const int warp = (blockIdx.x * blockDim.x + threadIdx.x) >> 5;
    const int lane = threadIdx.x & 31;
    if (warp >= N_EDGES + N_NODES) return;

    int r, c;
    float norm;
    if (warp < N_EDGES) {
        r = edge_at(ei, warp);             // row = source
        c = edge_at(ei, N_EDGES + warp);   // col = target
        norm = g_dinv[r] * g_dinv[c];
    } else {
        r = c = warp - N_EDGES;            // self loop
        float d = g_dinv[r];
        norm = d * d;
    }

    const float4* src = reinterpret_cast<const float4*>(g_xw + (size_t)r * D);
    float4 v = src[lane];
    float4 m = make_float4(v.x * norm, v.y * norm, v.z * norm, v.w * norm);
    float4* dst = reinterpret_cast<float4*>(g_agg + (size_t)c * D) + lane;
#if __CUDA_ARCH__ >= 900
    atomicAdd(dst, m);                     // vector RED
#else
    float* d4 = reinterpret_cast<float*>(dst);
    atomicAdd(d4 + 0, m.x); atomicAdd(d4 + 1, m.y);
    atomicAdd(d4 + 2, m.z); atomicAdd(d4 + 3, m.w);
#endif
}

// ---------------- column stats: sum and sumsq per feature --------------------
__global__ __launch_bounds__(D) void k_stats() {
    const int c = threadIdx.x;
    float s = 0.f, ss = 0.f;
    for (int r = blockIdx.x; r < N_NODES; r += gridDim.x) {
        float v = g_agg[(size_t)r * D + c];
        s += v;
        ss += v * v;
    }
    atomicAdd(&g_colsum[c], s);
    atomicAdd(&g_colss[c], ss);
}

__global__ __launch_bounds__(D) void k_finalize_stats() {
    const int c = threadIdx.x;
    float m = g_colsum[c] * (1.0f / N_NODES);
    g_mean[c] = m;
    float ssc = g_colss[c] - (float)N_NODES * m * m;  // sum (v-m)^2
    __shared__ float red[D];
    red[c] = ssc;
    __syncthreads();
    for (int off = D / 2; off > 0; off >>= 1) {
        if (c < off) red[c] += red[c + off];
        __syncthreads();
    }
    if (c == 0) g_scale = rsqrtf(EPS + red[0] * (1.0f / N_NODES));
}

// ---------------- normalize + relu + residual ---------------------------------
__global__ void k_output(float* __restrict__ out) {
    const int idx = blockIdx.x * blockDim.x + threadIdx.x;
    const int n4 = N_NODES * D / 4;
    if (idx >= n4) return;
    const int c = (idx & (D / 4 - 1)) * 4;
    const float scale = g_scale;
    float4 v = reinterpret_cast<const float4*>(g_agg)[idx];
    float o0 = (v.x - g_mean[c + 0]) * scale;
    float o1 = (v.y - g_mean[c + 1]) * scale;
    float o2 = (v.z - g_mean[c + 2]) * scale;
    float o3 = (v.w - g_mean[c + 3]) * scale;
    float4 y;
    y.x = fmaxf(o0, 0.f) + o0;
    y.y = fmaxf(o1, 0.f) + o1;
    y.z = fmaxf(o2, 0.f) + o2;
    y.w = fmaxf(o3, 0.f) + o3;
    reinterpret_cast<float4*>(out)[idx] = y;
}

// ---------------- launch -------------------------------------------------------
extern "C" void kernel_launch(void* const* d_in, const int* in_sizes, int n_in,
                              void* d_out, int out_size) {
    // identify inputs by element count, not position
    const float* x  = nullptr;
    const float* Wm = nullptr;
    const void*  ei = nullptr;
    for (int i = 0; i < n_in; i++) {
        if (in_sizes[i] == N_NODES * D)           x  = (const float*)d_in[i];
        else if (in_sizes[i] == D * D)            Wm = (const float*)d_in[i];
        else if (in_sizes[i] == 2 * N_EDGES ||
                 in_sizes[i] == 4 * N_EDGES)      ei = d_in[i];
    }
    if (!x)  x  = (const float*)d_in[0];
    if (!Wm) Wm = (const float*)d_in[1];
    if (!ei) ei = d_in[2];
    float* out = (float*)d_out;

    k_zero<<<1184, 256>>>((const int*)ei);
    k_degree<<<(N_EDGES + 255) / 256, 256>>>(ei);
    k_dinv<<<(N_NODES + 255) / 256, 256>>>();

    dim3 ggrid((N_NODES + GM - 1) / GM, D / GN);
    k_gemm<<<ggrid, 256>>>(x, Wm);

    const int items = N_EDGES + N_NODES;
    k_scatter<<<(items + 7) / 8, 256>>>(ei);   // warp per item

    k_stats<<<592, D>>>();
    k_finalize_stats<<<1, D>>>();

    const int n4 = N_NODES * D / 4;
    k_output<<<(n4 + 255) / 256, 256>>>(out);
}

// round 14
// speedup vs baseline: 1.8566x; 1.5659x over previous
#include <cuda_runtime.h>
#include <cstdint>

#define N_NODES 50000
#define N_EDGES 600000
#define D 128
#define EPS 1e-5f

#define SCAN_B 256
#define SCAN_NBLK ((N_NODES + SCAN_B - 1) / SCAN_B)   // 196

// ---------------- scratch (static device globals; no allocation) -------------
// NEVER passed as kernel arguments from host (GB300 ATS would silently write
// the host shadow). Referenced directly in device code.
__device__ __align__(16) float g_xw[(size_t)N_NODES * D];   // x @ W^T
__device__ __align__(16) float g_agg[(size_t)N_NODES * D];  // aggregated rows
__device__ int   g_degi[N_NODES];
__device__ float g_dinv[N_NODES];
__device__ int   g_off[N_NODES + 1];   // CSR offsets (by target node)
__device__ int   g_cur[N_NODES];       // fill cursors
__device__ int   g_src[N_EDGES];       // CSR data: source ids
__device__ int   g_bsum[SCAN_NBLK];    // scan block sums
__device__ int   g_boff[SCAN_NBLK];    // scan block offsets
__device__ float g_colsum[D];
__device__ float g_colss[D];
__device__ float g_mean[D];
__device__ float g_scale;
__device__ int   g_is64;

// ---------------- edge dtype helper (int64 vs int32 storage) -----------------
__device__ __forceinline__ int edge_at(const void* ei, int idx) {
    int v;
    if (g_is64) v = (int)__ldg(&((const long long*)ei)[idx]);
    else        v = __ldg(&((const int*)ei)[idx]);
    return (v < 0) ? 0 : (v >= N_NODES ? N_NODES - 1 : v);  // never fault
}

// ---------------- zero small scratch + dtype sniff (replay-safe) --------------
__global__ void k_zero(const int* __restrict__ ei32) {
    int idx = blockIdx.x * blockDim.x + threadIdx.x;
    int stride = gridDim.x * blockDim.x;
    if (idx == 0) {
        int all_zero = 1;
        for (int i = 0; i < 256; i++)
            if (__ldg(&ei32[2 * i + 1]) != 0) { all_zero = 0; break; }
        g_is64 = all_zero;
    }
    for (int i = idx; i < N_NODES; i += stride) g_degi[i] = 0;
    if (idx < D) { g_colsum[idx] = 0.f; g_colss[idx] = 0.f; }
}

// ---------------- in-degree histogram (int atomics) ---------------------------
__global__ void k_degree(const void* __restrict__ ei) {
    int e = blockIdx.x * blockDim.x + threadIdx.x;
    if (e < N_EDGES) atomicAdd(&g_degi[edge_at(ei, N_EDGES + e)], 1);
}

// ---------------- two-level exclusive scan ------------------------------------
__global__ __launch_bounds__(SCAN_B) void k_scan1() {
    __shared__ int sm[SCAN_B];
    const int t = threadIdx.x;
    const int n = blockIdx.x * SCAN_B + t;
    int v = (n < N_NODES) ? g_degi[n] : 0;
    sm[t] = v;
    __syncthreads();
    for (int off = 1; off < SCAN_B; off <<= 1) {     // Hillis-Steele inclusive
        int w = (t >= off) ? sm[t - off] : 0;
        __syncthreads();
        sm[t] += w;
        __syncthreads();
    }
    if (n < N_NODES) g_off[n] = sm[t] - v;           // exclusive, block-local
    if (t == SCAN_B - 1) g_bsum[blockIdx.x] = sm[t];
}

__global__ __launch_bounds__(SCAN_B) void k_scan2() {
    __shared__ int sm[SCAN_B];
    const int t = threadIdx.x;
    int v = (t < SCAN_NBLK) ? g_bsum[t] : 0;
    sm[t] = v;
    __syncthreads();
    for (int off = 1; off < SCAN_B; off <<= 1) {
        int w = (t >= off) ? sm[t - off] : 0;
        __syncthreads();
        sm[t] += w;
        __syncthreads();
    }
    if (t < SCAN_NBLK) g_boff[t] = sm[t] - v;        // exclusive
}

__global__ __launch_bounds__(SCAN_B) void k_scan3() {
    const int n = blockIdx.x * SCAN_B + threadIdx.x;
    if (n < N_NODES) {
        int o = g_off[n] + g_boff[blockIdx.x];
        g_off[n] = o;
        g_cur[n] = o;
        g_dinv[n] = rsqrtf((float)g_degi[n] + 1.0f); // +1 self loop
    }
    if (n == 0) g_off[N_NODES] = N_EDGES;            // total known statically
}

// ---------------- CSR fill (int atomics, 12.8us measured) ---------------------
__global__ void k_fill(const void* __restrict__ ei) {
    int e = blockIdx.x * blockDim.x + threadIdx.x;
    if (e < N_EDGES) {
        int r = edge_at(ei, e);              // source
        int c = edge_at(ei, N_EDGES + e);    // target
        int pos = atomicAdd(&g_cur[c], 1);
        g_src[pos] = r;
    }
}

// ---------------- GEMM: g_xw = x @ W^T  (FFMA2, validated R11/R12) ------------
#define GM 128
#define GN 64
#define GK 32
#define SA_STRIDE (GM + 2)
#define SB_STRIDE (GN + 4)
__global__ __launch_bounds__(256) void k_gemm(const float* __restrict__ A,
                                              const float* __restrict__ Wm) {
    __shared__ float sA[GK][SA_STRIDE];
    __shared__ float sB[GK][SB_STRIDE];
    const int tid = threadIdx.x;
    const int brow = blockIdx.x * GM;
    const int bcol = blockIdx.y * GN;
    const int tx = tid & 15;
    const int ty = tid >> 4;

    unsigned long long acc2[4][4];
#pragma unroll
    for (int i2 = 0; i2 < 4; i2++)
#pragma unroll
        for (int j = 0; j < 4; j++) acc2[i2][j] = 0ULL;

    for (int k0 = 0; k0 < D; k0 += GK) {
#pragma unroll
        for (int p = 0; p < 4; p++) {
            int r  = (tid >> 3) + p * 32;
            int kk = (tid & 7) * 4;
            int gr = brow + r;
            float4 v = make_float4(0.f, 0.f, 0.f, 0.f);
            if (gr < N_NODES)
                v = *reinterpret_cast<const float4*>(A + (size_t)gr * D + k0 + kk);
            sA[kk + 0][r] = v.x; sA[kk + 1][r] = v.y;
            sA[kk + 2][r] = v.z; sA[kk + 3][r] = v.w;
        }
#pragma unroll
        for (int p = 0; p < 2; p++) {
            int r  = (tid >> 3) + p * 32;
            int kk = (tid & 7) * 4;
            float4 v = *reinterpret_cast<const float4*>(Wm + (size_t)(bcol + r) * D + k0 + kk);
            sB[kk + 0][r] = v.x; sB[kk + 1][r] = v.y;
            sB[kk + 2][r] = v.z; sB[kk + 3][r] = v.w;
        }
        __syncthreads();

#pragma unroll
        for (int kk = 0; kk < GK; kk++) {
            unsigned long long a2[4];
            const float* arow = &sA[kk][ty * 8];
#pragma unroll
            for (int q = 0; q < 4; q++)
                a2[q] = *reinterpret_cast<const unsigned long long*>(arow + 2 * q);

            float4 b4 = *reinterpret_cast<const float4*>(&sB[kk][tx * 4]);
            unsigned long long bb[4];
            asm("mov.b64 %0, {%1, %1};" : "=l"(bb[0]) : "f"(b4.x));
            asm("mov.b64 %0, {%1, %1};" : "=l"(bb[1]) : "f"(b4.y));
            asm("mov.b64 %0, {%1, %1};" : "=l"(bb[2]) : "f"(b4.z));
            asm("mov.b64 %0, {%1, %1};" : "=l"(bb[3]) : "f"(b4.w));

#pragma unroll
            for (int i2 = 0; i2 < 4; i2++)
#pragma unroll
                for (int j = 0; j < 4; j++)
                    asm("fma.rn.f32x2 %0, %1, %2, %0;"
                        : "+l"(acc2[i2][j]) : "l"(a2[i2]), "l"(bb[j]));
        }
        __syncthreads();
    }

#pragma unroll
    for (int i2 = 0; i2 < 4; i2++) {
        float lo[4], hi[4];
#pragma unroll
        for (int j = 0; j < 4; j++)
            asm("mov.b64 {%0, %1}, %2;" : "=f"(lo[j]), "=f"(hi[j]) : "l"(acc2[i2][j]));
        int gr = brow + ty * 8 + 2 * i2;
        if (gr < N_NODES)
            *reinterpret_cast<float4*>(g_xw + (size_t)gr * D + bcol + tx * 4) =
                make_float4(lo[0], lo[1], lo[2], lo[3]);
        if (gr + 1 < N_NODES)
            *reinterpret_cast<float4*>(g_xw + (size_t)(gr + 1) * D + bcol + tx * 4) =
                make_float4(hi[0], hi[1], hi[2], hi[3]);
    }
}

// ---------------- pull aggregate (warp/node, MLP=4) + fused stats -------------
__global__ __launch_bounds__(256) void k_agg() {
    const int lane = threadIdx.x & 31;
    const int warp0 = (blockIdx.x * blockDim.x + threadIdx.x) >> 5;
    const int nwarps = gridDim.x * (blockDim.x >> 5);

    float s[4]  = {0.f, 0.f, 0.f, 0.f};
    float ss[4] = {0.f, 0.f, 0.f, 0.f};

    for (int v = warp0; v < N_NODES; v += nwarps) {
        float dv = g_dinv[v];
        float4 acc = reinterpret_cast<const float4*>(g_xw + (size_t)v * D)[lane];
        acc.x *= dv; acc.y *= dv; acc.z *= dv; acc.w *= dv;   // self loop

        int e = g_off[v];
        const int e1 = g_off[v + 1];

        // unrolled x4: four independent (idx, dinv, row) fetch chains in flight
        for (; e + 4 <= e1; e += 4) {
            int u0 = g_src[e + 0], u1 = g_src[e + 1];
            int u2 = g_src[e + 2], u3 = g_src[e + 3];
            float d0 = g_dinv[u0], d1 = g_dinv[u1];
            float d2 = g_dinv[u2], d3 = g_dinv[u3];
            float4 x0 = reinterpret_cast<const float4*>(g_xw + (size_t)u0 * D)[lane];
            float4 x1 = reinterpret_cast<const float4*>(g_xw + (size_t)u1 * D)[lane];
            float4 x2 = reinterpret_cast<const float4*>(g_xw + (size_t)u2 * D)[lane];
            float4 x3 = reinterpret_cast<const float4*>(g_xw + (size_t)u3 * D)[lane];
            acc.x = fmaf(d0, x0.x, fmaf(d1, x1.x, fmaf(d2, x2.x, fmaf(d3, x3.x, acc.x))));
            acc.y = fmaf(d0, x0.y, fmaf(d1, x1.y, fmaf(d2, x2.y, fmaf(d3, x3.y, acc.y))));
            acc.z = fmaf(d0, x0.z, fmaf(d1, x1.z, fmaf(d2, x2.z, fmaf(d3, x3.z, acc.z))));
            acc.w = fmaf(d0, x0.w, fmaf(d1, x1.w, fmaf(d2, x2.w, fmaf(d3, x3.w, acc.w))));
        }
        for (; e < e1; e++) {
            int u = g_src[e];
            float du = g_dinv[u];
            float4 xu = reinterpret_cast<const float4*>(g_xw + (size_t)u * D)[lane];
            acc.x = fmaf(du, xu.x, acc.x);
            acc.y = fmaf(du, xu.y, acc.y);
            acc.z = fmaf(du, xu.z, acc.z);
            acc.w = fmaf(du, xu.w, acc.w);
        }

        acc.x *= dv; acc.y *= dv; acc.z *= dv; acc.w *= dv;
        reinterpret_cast<float4*>(g_agg + (size_t)v * D)[lane] = acc;

        s[0] += acc.x; s[1] += acc.y; s[2] += acc.z; s[3] += acc.w;
        ss[0] += acc.x * acc.x; ss[1] += acc.y * acc.y;
        ss[2] += acc.z * acc.z; ss[3] += acc.w * acc.w;
    }

    __shared__ float sm_s[D], sm_ss[D];
    if (threadIdx.x < D) { sm_s[threadIdx.x] = 0.f; sm_ss[threadIdx.x] = 0.f; }
    __syncthreads();
#pragma unroll
    for (int q = 0; q < 4; q++) {
        atomicAdd(&sm_s[lane * 4 + q], s[q]);
        atomicAdd(&sm_ss[lane * 4 + q], ss[q]);
    }
    __syncthreads();
    if (threadIdx.x < D) {
        atomicAdd(&g_colsum[threadIdx.x], sm_s[threadIdx.x]);
        atomicAdd(&g_colss[threadIdx.x],  sm_ss[threadIdx.x]);
    }
}

// ---------------- finalize PairNorm stats -------------------------------------
__global__ __launch_bounds__(D) void k_finalize_stats() {
    const int c = threadIdx.x;
    float m = g_colsum[c] * (1.0f / N_NODES);
    g_mean[c] = m;
    float ssc = g_colss[c] - (float)N_NODES * m * m;
    __shared__ float red[D];
    red[c] = ssc;
    __syncthreads();
    for (int off = D / 2; off > 0; off >>= 1) {
        if (c < off) red[c] += red[c + off];
        __syncthreads();
    }
    if (c == 0) g_scale = rsqrtf(EPS + red[0] * (1.0f / N_NODES));
}

// ---------------- normalize + relu + residual ---------------------------------
__global__ void k_output(float* __restrict__ out) {
    const int idx = blockIdx.x * blockDim.x + threadIdx.x;
    const int n4 = N_NODES * D / 4;
    if (idx >= n4) return;
    const int c = (idx & (D / 4 - 1)) * 4;
    const float scale = g_scale;
    float4 v = reinterpret_cast<const float4*>(g_agg)[idx];
    float o0 = (v.x - g_mean[c + 0]) * scale;
    float o1 = (v.y - g_mean[c + 1]) * scale;
    float o2 = (v.z - g_mean[c + 2]) * scale;
    float o3 = (v.w - g_mean[c + 3]) * scale;
    float4 y;
    y.x = fmaxf(o0, 0.f) + o0;
    y.y = fmaxf(o1, 0.f) + o1;
    y.z = fmaxf(o2, 0.f) + o2;
    y.w = fmaxf(o3, 0.f) + o3;
    reinterpret_cast<float4*>(out)[idx] = y;
}

// ---------------- launch -------------------------------------------------------
extern "C" void kernel_launch(void* const* d_in, const int* in_sizes, int n_in,
                              void* d_out, int out_size) {
    const float* x  = nullptr;
    const float* Wm = nullptr;
    const void*  ei = nullptr;
    for (int i = 0; i < n_in; i++) {
        if (in_sizes[i] == N_NODES * D)           x  = (const float*)d_in[i];
        else if (in_sizes[i] == D * D)            Wm = (const float*)d_in[i];
        else if (in_sizes[i] == 2 * N_EDGES ||
                 in_sizes[i] == 4 * N_EDGES)      ei = d_in[i];
    }
    if (!x)  x  = (const float*)d_in[0];
    if (!Wm) Wm = (const float*)d_in[1];
    if (!ei) ei = d_in[2];
    float* out = (float*)d_out;

    k_zero<<<196, 256>>>((const int*)ei);
    k_degree<<<(N_EDGES + 255) / 256, 256>>>(ei);
    k_scan1<<<SCAN_NBLK, SCAN_B>>>();
    k_scan2<<<1, SCAN_B>>>();
    k_scan3<<<SCAN_NBLK, SCAN_B>>>();
    k_fill<<<(N_EDGES + 255) / 256, 256>>>(ei);

    dim3 ggrid((N_NODES + GM - 1) / GM, D / GN);
    k_gemm<<<ggrid, 256>>>(x, Wm);

    k_agg<<<1184, 256>>>();
    k_finalize_stats<<<1, D>>>();

    const int n4 = N_NODES * D / 4;
    k_output<<<(n4 + 255) / 256, 256>>>(out);
}

// round 15
// speedup vs baseline: 1.9245x; 1.0366x over previous
#include <cuda_runtime.h>
#include <cstdint>

#define N_NODES 50000
#define N_EDGES 600000
#define D 128
#define EPS 1e-5f

#define SCAN_B 256
#define SCAN_NBLK ((N_NODES + SCAN_B - 1) / SCAN_B)   // 196

// ---------------- scratch (static device globals; no allocation) -------------
// NEVER passed as kernel arguments from host (GB300 ATS would silently write
// the host shadow). Referenced directly in device code.
__device__ __align__(16) float g_xw[(size_t)N_NODES * D];   // x @ W^T
__device__ __align__(16) float g_agg[(size_t)N_NODES * D];  // aggregated rows
__device__ int   g_degi[N_NODES];
__device__ float g_dinv[N_NODES];
__device__ int   g_off[N_NODES + 1];   // CSR offsets (by target node)
__device__ int   g_cur[N_NODES];       // fill cursors
__device__ int   g_src[N_EDGES];       // CSR data: source ids
__device__ int   g_bsum[SCAN_NBLK];    // scan block sums
__device__ float g_colsum[D];
__device__ float g_colss[D];
__device__ float g_mean[D];
__device__ float g_scale;
__device__ int   g_is64;

// ---------------- edge dtype helper (int64 vs int32 storage) -----------------
__device__ __forceinline__ int edge_at(const void* ei, int idx) {
    int v;
    if (g_is64) v = (int)__ldg(&((const long long*)ei)[idx]);
    else        v = __ldg(&((const int*)ei)[idx]);
    return (v < 0) ? 0 : (v >= N_NODES ? N_NODES - 1 : v);  // never fault
}

// ---------------- zero small scratch + dtype sniff (replay-safe) --------------
__global__ void k_zero(const int* __restrict__ ei32) {
    int idx = blockIdx.x * blockDim.x + threadIdx.x;
    int stride = gridDim.x * blockDim.x;
    if (idx == 0) {
        int all_zero = 1;
        for (int i = 0; i < 256; i++)
            if (__ldg(&ei32[2 * i + 1]) != 0) { all_zero = 0; break; }
        g_is64 = all_zero;
    }
    for (int i = idx; i < N_NODES; i += stride) g_degi[i] = 0;
    if (idx < D) { g_colsum[idx] = 0.f; g_colss[idx] = 0.f; }
}

// ---------------- in-degree histogram (int atomics) ---------------------------
__global__ void k_degree(const void* __restrict__ ei) {
    int e = blockIdx.x * blockDim.x + threadIdx.x;
    if (e < N_EDGES) atomicAdd(&g_degi[edge_at(ei, N_EDGES + e)], 1);
}

// ---------------- scan level 1: per-block exclusive + block sums --------------
__global__ __launch_bounds__(SCAN_B) void k_scan1() {
    __shared__ int sm[SCAN_B];
    const int t = threadIdx.x;
    const int n = blockIdx.x * SCAN_B + t;
    int v = (n < N_NODES) ? g_degi[n] : 0;
    sm[t] = v;
    __syncthreads();
    for (int off = 1; off < SCAN_B; off <<= 1) {     // Hillis-Steele inclusive
        int w = (t >= off) ? sm[t - off] : 0;
        __syncthreads();
        sm[t] += w;
        __syncthreads();
    }
    if (n < N_NODES) g_off[n] = sm[t] - v;           // exclusive, block-local
    if (t == SCAN_B - 1) g_bsum[blockIdx.x] = sm[t];
}

// ---------------- scan level 2+3 fused: every block scans the 196 sums --------
__global__ __launch_bounds__(SCAN_B) void k_scan3() {
    __shared__ int sm[SCAN_B];
    const int t = threadIdx.x;
    int bv = (t < SCAN_NBLK) ? g_bsum[t] : 0;
    sm[t] = bv;
    __syncthreads();
    for (int off = 1; off < SCAN_B; off <<= 1) {     // redundant per block: trivial
        int w = (t >= off) ? sm[t - off] : 0;
        __syncthreads();
        sm[t] += w;
        __syncthreads();
    }
    const int boff = sm[blockIdx.x] - g_bsum[blockIdx.x];  // exclusive block offset
    const int n = blockIdx.x * SCAN_B + t;
    if (n < N_NODES) {
        int o = g_off[n] + boff;
        g_off[n] = o;
        g_cur[n] = o;
        g_dinv[n] = rsqrtf((float)g_degi[n] + 1.0f); // +1 self loop
    }
    if (n == 0) g_off[N_NODES] = N_EDGES;            // total known statically
}

// ---------------- CSR fill (int atomics, 12.8us measured) ---------------------
__global__ void k_fill(const void* __restrict__ ei) {
    int e = blockIdx.x * blockDim.x + threadIdx.x;
    if (e < N_EDGES) {
        int r = edge_at(ei, e);              // source
        int c = edge_at(ei, N_EDGES + e);    // target
        int pos = atomicAdd(&g_cur[c], 1);
        g_src[pos] = r;
    }
}

// ---------------- GEMM: g_xw = x @ W^T  (FFMA2, double-buffered smem) ---------
#define GM 128
#define GN 64
#define GK 16
#define SA_STRIDE (GM + 2)   // 130 floats: 8B-aligned rows for LDS.64 a-pairs
#define SB_STRIDE (GN + 4)   // 68 floats: 16B-aligned rows for LDS.128 b
__global__ __launch_bounds__(256) void k_gemm(const float* __restrict__ A,
                                              const float* __restrict__ Wm) {
    __shared__ float sA[2][GK][SA_STRIDE];   // 2*16*130*4 = 16.6KB
    __shared__ float sB[2][GK][SB_STRIDE];   // 2*16*68*4  =  8.7KB
    const int tid = threadIdx.x;
    const int brow = blockIdx.x * GM;
    const int bcol = blockIdx.y * GN;
    const int tx = tid & 15;      // cols tx*4 .. +3
    const int ty = tid >> 4;      // rows ty*8 .. +7
    const int lr  = tid >> 2;     // load row 0..63
    const int lkk = (tid & 3) * 4;// load k group

    unsigned long long acc2[4][4];
#pragma unroll
    for (int i2 = 0; i2 < 4; i2++)
#pragma unroll
        for (int j = 0; j < 4; j++) acc2[i2][j] = 0ULL;

    auto load_tiles = [&](int k0, int buf) {
#pragma unroll
        for (int p = 0; p < 2; p++) {            // A tile: 128 x 16
            int r = lr + p * 64;
            int gr = brow + r;
            float4 v = make_float4(0.f, 0.f, 0.f, 0.f);
            if (gr < N_NODES)
                v = *reinterpret_cast<const float4*>(A + (size_t)gr * D + k0 + lkk);
            sA[buf][lkk + 0][r] = v.x; sA[buf][lkk + 1][r] = v.y;
            sA[buf][lkk + 2][r] = v.z; sA[buf][lkk + 3][r] = v.w;
        }
        {                                        // B tile: 64 x 16
            float4 v = *reinterpret_cast<const float4*>(Wm + (size_t)(bcol + lr) * D + k0 + lkk);
            sB[buf][lkk + 0][lr] = v.x; sB[buf][lkk + 1][lr] = v.y;
            sB[buf][lkk + 2][lr] = v.z; sB[buf][lkk + 3][lr] = v.w;
        }
    };

    load_tiles(0, 0);
    __syncthreads();

#pragma unroll
    for (int it = 0; it < D / GK; it++) {        // 8 iterations
        const int buf = it & 1;
        if (it + 1 < D / GK) load_tiles((it + 1) * GK, buf ^ 1);  // overlap with compute

#pragma unroll
        for (int kk = 0; kk < GK; kk++) {
            unsigned long long a2[4];
            const float* arow = &sA[buf][kk][ty * 8];
#pragma unroll
            for (int q = 0; q < 4; q++)
                a2[q] = *reinterpret_cast<const unsigned long long*>(arow + 2 * q);

            float4 b4 = *reinterpret_cast<const float4*>(&sB[buf][kk][tx * 4]);
            unsigned long long bb[4];
            asm("mov.b64 %0, {%1, %1};" : "=l"(bb[0]) : "f"(b4.x));
            asm("mov.b64 %0, {%1, %1};" : "=l"(bb[1]) : "f"(b4.y));
            asm("mov.b64 %0, {%1, %1};" : "=l"(bb[2]) : "f"(b4.z));
            asm("mov.b64 %0, {%1, %1};" : "=l"(bb[3]) : "f"(b4.w));

#pragma unroll
            for (int i2 = 0; i2 < 4; i2++)
#pragma unroll
                for (int j = 0; j < 4; j++)
                    asm("fma.rn.f32x2 %0, %1, %2, %0;"
                        : "+l"(acc2[i2][j]) : "l"(a2[i2]), "l"(bb[j]));
        }
        __syncthreads();   // nxt stores visible; cur reads done before overwrite
    }

#pragma unroll
    for (int i2 = 0; i2 < 4; i2++) {
        float lo[4], hi[4];
#pragma unroll
        for (int j = 0; j < 4; j++)
            asm("mov.b64 {%0, %1}, %2;" : "=f"(lo[j]), "=f"(hi[j]) : "l"(acc2[i2][j]));
        int gr = brow + ty * 8 + 2 * i2;
        if (gr < N_NODES)
            *reinterpret_cast<float4*>(g_xw + (size_t)gr * D + bcol + tx * 4) =
                make_float4(lo[0], lo[1], lo[2], lo[3]);
        if (gr + 1 < N_NODES)
            *reinterpret_cast<float4*>(g_xw + (size_t)(gr + 1) * D + bcol + tx * 4) =
                make_float4(hi[0], hi[1], hi[2], hi[3]);
    }
}

// ---------------- pull aggregate (warp/node, MLP=4) + fused stats -------------
__global__ __launch_bounds__(256) void k_agg() {
    const int lane = threadIdx.x & 31;
    const int warp0 = (blockIdx.x * blockDim.x + threadIdx.x) >> 5;
    const int nwarps = gridDim.x * (blockDim.x >> 5);

    float s[4]  = {0.f, 0.f, 0.f, 0.f};
    float ss[4] = {0.f, 0.f, 0.f, 0.f};

    for (int v = warp0; v < N_NODES; v += nwarps) {
        float dv = g_dinv[v];
        float4 acc = reinterpret_cast<const float4*>(g_xw + (size_t)v * D)[lane];
        acc.x *= dv; acc.y *= dv; acc.z *= dv; acc.w *= dv;   // self loop

        int e = g_off[v];
        const int e1 = g_off[v + 1];

        for (; e + 4 <= e1; e += 4) {            // 4 independent fetch chains
            int u0 = g_src[e + 0], u1 = g_src[e + 1];
            int u2 = g_src[e + 2], u3 = g_src[e + 3];
            float d0 = g_dinv[u0], d1 = g_dinv[u1];
            float d2 = g_dinv[u2], d3 = g_dinv[u3];
            float4 x0 = reinterpret_cast<const float4*>(g_xw + (size_t)u0 * D)[lane];
            float4 x1 = reinterpret_cast<const float4*>(g_xw + (size_t)u1 * D)[lane];
            float4 x2 = reinterpret_cast<const float4*>(g_xw + (size_t)u2 * D)[lane];
            float4 x3 = reinterpret_cast<const float4*>(g_xw + (size_t)u3 * D)[lane];
            acc.x = fmaf(d0, x0.x, fmaf(d1, x1.x, fmaf(d2, x2.x, fmaf(d3, x3.x, acc.x))));
            acc.y = fmaf(d0, x0.y, fmaf(d1, x1.y, fmaf(d2, x2.y, fmaf(d3, x3.y, acc.y))));
            acc.z = fmaf(d0, x0.z, fmaf(d1, x1.z, fmaf(d2, x2.z, fmaf(d3, x3.z, acc.z))));
            acc.w = fmaf(d0, x0.w, fmaf(d1, x1.w, fmaf(d2, x2.w, fmaf(d3, x3.w, acc.w))));
        }
        for (; e < e1; e++) {
            int u = g_src[e];
            float du = g_dinv[u];
            float4 xu = reinterpret_cast<const float4*>(g_xw + (size_t)u * D)[lane];
            acc.x = fmaf(du, xu.x, acc.x);
            acc.y = fmaf(du, xu.y, acc.y);
            acc.z = fmaf(du, xu.z, acc.z);
            acc.w = fmaf(du, xu.w, acc.w);
        }

        acc.x *= dv; acc.y *= dv; acc.z *= dv; acc.w *= dv;
        reinterpret_cast<float4*>(g_agg + (size_t)v * D)[lane] = acc;

        s[0] += acc.x; s[1] += acc.y; s[2] += acc.z; s[3] += acc.w;
        ss[0] += acc.x * acc.x; ss[1] += acc.y * acc.y;
        ss[2] += acc.z * acc.z; ss[3] += acc.w * acc.w;
    }

    __shared__ float sm_s[D], sm_ss[D];
    if (threadIdx.x < D) { sm_s[threadIdx.x] = 0.f; sm_ss[threadIdx.x] = 0.f; }
    __syncthreads();
#pragma unroll
    for (int q = 0; q < 4; q++) {
        atomicAdd(&sm_s[lane * 4 + q], s[q]);
        atomicAdd(&sm_ss[lane * 4 + q], ss[q]);
    }
    __syncthreads();
    if (threadIdx.x < D) {
        atomicAdd(&g_colsum[threadIdx.x], sm_s[threadIdx.x]);
        atomicAdd(&g_colss[threadIdx.x],  sm_ss[threadIdx.x]);
    }
}

// ---------------- finalize PairNorm stats -------------------------------------
__global__ __launch_bounds__(D) void k_finalize_stats() {
    const int c = threadIdx.x;
    float m = g_colsum[c] * (1.0f / N_NODES);
    g_mean[c] = m;
    float ssc = g_colss[c] - (float)N_NODES * m * m;
    __shared__ float red[D];
    red[c] = ssc;
    __syncthreads();
    for (int off = D / 2; off > 0; off >>= 1) {
        if (c < off) red[c] += red[c + off];
        __syncthreads();
    }
    if (c == 0) g_scale = rsqrtf(EPS + red[0] * (1.0f / N_NODES));
}

// ---------------- normalize + relu + residual ---------------------------------
__global__ void k_output(float* __restrict__ out) {
    const int idx = blockIdx.x * blockDim.x + threadIdx.x;
    const int n4 = N_NODES * D / 4;
    if (idx >= n4) return;
    const int c = (idx & (D / 4 - 1)) * 4;
    const float scale = g_scale;
    float4 v = reinterpret_cast<const float4*>(g_agg)[idx];
    float o0 = (v.x - g_mean[c + 0]) * scale;
    float o1 = (v.y - g_mean[c + 1]) * scale;
    float o2 = (v.z - g_mean[c + 2]) * scale;
    float o3 = (v.w - g_mean[c + 3]) * scale;
    float4 y;
    y.x = fmaxf(o0, 0.f) + o0;
    y.y = fmaxf(o1, 0.f) + o1;
    y.z = fmaxf(o2, 0.f) + o2;
    y.w = fmaxf(o3, 0.f) + o3;
    reinterpret_cast<float4*>(out)[idx] = y;
}

// ---------------- launch -------------------------------------------------------
extern "C" void kernel_launch(void* const* d_in, const int* in_sizes, int n_in,
                              void* d_out, int out_size) {
    const float* x  = nullptr;
    const float* Wm = nullptr;
    const void*  ei = nullptr;
    for (int i = 0; i < n_in; i++) {
        if (in_sizes[i] == N_NODES * D)           x  = (const float*)d_in[i];
        else if (in_sizes[i] == D * D)            Wm = (const float*)d_in[i];
        else if (in_sizes[i] == 2 * N_EDGES ||
                 in_sizes[i] == 4 * N_EDGES)      ei = d_in[i];
    }
    if (!x)  x  = (const float*)d_in[0];
    if (!Wm) Wm = (const float*)d_in[1];
    if (!ei) ei = d_in[2];
    float* out = (float*)d_out;

    k_zero<<<196, 256>>>((const int*)ei);
    k_degree<<<(N_EDGES + 255) / 256, 256>>>(ei);
    k_scan1<<<SCAN_NBLK, SCAN_B>>>();
    k_scan3<<<SCAN_NBLK, SCAN_B>>>();
    k_fill<<<(N_EDGES + 255) / 256, 256>>>(ei);

    dim3 ggrid((N_NODES + GM - 1) / GM, D / GN);
    k_gemm<<<ggrid, 256>>>(x, Wm);

    k_agg<<<1184, 256>>>();
    k_finalize_stats<<<1, D>>>();

    const int n4 = N_NODES * D / 4;
    k_output<<<(n4 + 255) / 256, 256>>>(out);
}

// round 16
// speedup vs baseline: 2.0726x; 1.0769x over previous
#include <cuda_runtime.h>
#include <cstdint>

#define N_NODES 50000
#define N_EDGES 600000
#define D 128
#define EPS 1e-5f

#define SCAN_B 256
#define SCAN_NBLK ((N_NODES + SCAN_B - 1) / SCAN_B)   // 196

// ---------------- scratch (static device globals; no allocation) -------------
// NEVER passed as kernel arguments from host (GB300 ATS would silently write
// the host shadow). Referenced directly in device code.
__device__ __align__(16) float g_xw[(size_t)N_NODES * D];   // x @ W^T
__device__ __align__(16) float g_agg[(size_t)N_NODES * D];  // aggregated rows
__device__ int   g_degi[N_NODES];
__device__ float g_dinv[N_NODES];
__device__ int   g_off[N_NODES + 1];   // CSR offsets (by target node)
__device__ int   g_cur[N_NODES];       // fill cursors
__device__ int   g_src[N_EDGES];       // CSR data: source ids
__device__ int   g_bsum[SCAN_NBLK];    // scan block sums
__device__ float g_colsum[D];
__device__ float g_colss[D];
__device__ int   g_is64;

// ---------------- edge dtype helper (int64 vs int32 storage) -----------------
__device__ __forceinline__ int edge_at(const void* ei, int idx) {
    int v;
    if (g_is64) v = (int)__ldg(&((const long long*)ei)[idx]);
    else        v = __ldg(&((const int*)ei)[idx]);
    return (v < 0) ? 0 : (v >= N_NODES ? N_NODES - 1 : v);  // never fault
}

// ---------------- zero small scratch + dtype sniff (replay-safe) --------------
__global__ void k_zero(const int* __restrict__ ei32) {
    int idx = blockIdx.x * blockDim.x + threadIdx.x;
    int stride = gridDim.x * blockDim.x;
    if (idx == 0) {
        int all_zero = 1;
        for (int i = 0; i < 256; i++)
            if (__ldg(&ei32[2 * i + 1]) != 0) { all_zero = 0; break; }
        g_is64 = all_zero;
    }
    for (int i = idx; i < N_NODES; i += stride) g_degi[i] = 0;
    if (idx < D) { g_colsum[idx] = 0.f; g_colss[idx] = 0.f; }
}

// ---------------- in-degree histogram (int atomics) ---------------------------
__global__ void k_degree(const void* __restrict__ ei) {
    int e = blockIdx.x * blockDim.x + threadIdx.x;
    if (e < N_EDGES) atomicAdd(&g_degi[edge_at(ei, N_EDGES + e)], 1);
}

// ---------------- scan level 1: per-block exclusive + block sums --------------
__global__ __launch_bounds__(SCAN_B) void k_scan1() {
    __shared__ int sm[SCAN_B];
    const int t = threadIdx.x;
    const int n = blockIdx.x * SCAN_B + t;
    int v = (n < N_NODES) ? g_degi[n] : 0;
    sm[t] = v;
    __syncthreads();
    for (int off = 1; off < SCAN_B; off <<= 1) {     // Hillis-Steele inclusive
        int w = (t >= off) ? sm[t - off] : 0;
        __syncthreads();
        sm[t] += w;
        __syncthreads();
    }
    if (n < N_NODES) g_off[n] = sm[t] - v;           // exclusive, block-local
    if (t == SCAN_B - 1) g_bsum[blockIdx.x] = sm[t];
}

// ---------------- scan level 2+3 fused: every block scans the 196 sums --------
__global__ __launch_bounds__(SCAN_B) void k_scan3() {
    __shared__ int sm[SCAN_B];
    const int t = threadIdx.x;
    int bv = (t < SCAN_NBLK) ? g_bsum[t] : 0;
    sm[t] = bv;
    __syncthreads();
    for (int off = 1; off < SCAN_B; off <<= 1) {
        int w = (t >= off) ? sm[t - off] : 0;
        __syncthreads();
        sm[t] += w;
        __syncthreads();
    }
    const int boff = sm[blockIdx.x] - g_bsum[blockIdx.x];  // exclusive block offset
    const int n = blockIdx.x * SCAN_B + t;
    if (n < N_NODES) {
        int o = g_off[n] + boff;
        g_off[n] = o;
        g_cur[n] = o;
        g_dinv[n] = rsqrtf((float)g_degi[n] + 1.0f); // +1 self loop
    }
    if (n == 0) g_off[N_NODES] = N_EDGES;            // total known statically
}

// ---------------- CSR fill (int atomics) ---------------------------------------
__global__ void k_fill(const void* __restrict__ ei) {
    int e = blockIdx.x * blockDim.x + threadIdx.x;
    if (e < N_EDGES) {
        int r = edge_at(ei, e);              // source
        int c = edge_at(ei, N_EDGES + e);    // target
        int pos = atomicAdd(&g_cur[c], 1);
        g_src[pos] = r;
    }
}

// ---------------- GEMM: g_xw = x @ W^T  (FFMA2, double-buffered; frozen R14) --
#define GM 128
#define GN 64
#define GK 16
#define SA_STRIDE (GM + 2)
#define SB_STRIDE (GN + 4)
__global__ __launch_bounds__(256) void k_gemm(const float* __restrict__ A,
                                              const float* __restrict__ Wm) {
    __shared__ float sA[2][GK][SA_STRIDE];
    __shared__ float sB[2][GK][SB_STRIDE];
    const int tid = threadIdx.x;
    const int brow = blockIdx.x * GM;
    const int bcol = blockIdx.y * GN;
    const int tx = tid & 15;
    const int ty = tid >> 4;
    const int lr  = tid >> 2;
    const int lkk = (tid & 3) * 4;

    unsigned long long acc2[4][4];
#pragma unroll
    for (int i2 = 0; i2 < 4; i2++)
#pragma unroll
        for (int j = 0; j < 4; j++) acc2[i2][j] = 0ULL;

    auto load_tiles = [&](int k0, int buf) {
#pragma unroll
        for (int p = 0; p < 2; p++) {
            int r = lr + p * 64;
            int gr = brow + r;
            float4 v = make_float4(0.f, 0.f, 0.f, 0.f);
            if (gr < N_NODES)
                v = *reinterpret_cast<const float4*>(A + (size_t)gr * D + k0 + lkk);
            sA[buf][lkk + 0][r] = v.x; sA[buf][lkk + 1][r] = v.y;
            sA[buf][lkk + 2][r] = v.z; sA[buf][lkk + 3][r] = v.w;
        }
        {
            float4 v = *reinterpret_cast<const float4*>(Wm + (size_t)(bcol + lr) * D + k0 + lkk);
            sB[buf][lkk + 0][lr] = v.x; sB[buf][lkk + 1][lr] = v.y;
            sB[buf][lkk + 2][lr] = v.z; sB[buf][lkk + 3][lr] = v.w;
        }
    };

    load_tiles(0, 0);
    __syncthreads();

#pragma unroll
    for (int it = 0; it < D / GK; it++) {
        const int buf = it & 1;
        if (it + 1 < D / GK) load_tiles((it + 1) * GK, buf ^ 1);

#pragma unroll
        for (int kk = 0; kk < GK; kk++) {
            unsigned long long a2[4];
            const float* arow = &sA[buf][kk][ty * 8];
#pragma unroll
            for (int q = 0; q < 4; q++)
                a2[q] = *reinterpret_cast<const unsigned long long*>(arow + 2 * q);

            float4 b4 = *reinterpret_cast<const float4*>(&sB[buf][kk][tx * 4]);
            unsigned long long bb[4];
            asm("mov.b64 %0, {%1, %1};" : "=l"(bb[0]) : "f"(b4.x));
            asm("mov.b64 %0, {%1, %1};" : "=l"(bb[1]) : "f"(b4.y));
            asm("mov.b64 %0, {%1, %1};" : "=l"(bb[2]) : "f"(b4.z));
            asm("mov.b64 %0, {%1, %1};" : "=l"(bb[3]) : "f"(b4.w));

#pragma unroll
            for (int i2 = 0; i2 < 4; i2++)
#pragma unroll
                for (int j = 0; j < 4; j++)
                    asm("fma.rn.f32x2 %0, %1, %2, %0;"
                        : "+l"(acc2[i2][j]) : "l"(a2[i2]), "l"(bb[j]));
        }
        __syncthreads();
    }

#pragma unroll
    for (int i2 = 0; i2 < 4; i2++) {
        float lo[4], hi[4];
#pragma unroll
        for (int j = 0; j < 4; j++)
            asm("mov.b64 {%0, %1}, %2;" : "=f"(lo[j]), "=f"(hi[j]) : "l"(acc2[i2][j]));
        int gr = brow + ty * 8 + 2 * i2;
        if (gr < N_NODES)
            *reinterpret_cast<float4*>(g_xw + (size_t)gr * D + bcol + tx * 4) =
                make_float4(lo[0], lo[1], lo[2], lo[3]);
        if (gr + 1 < N_NODES)
            *reinterpret_cast<float4*>(g_xw + (size_t)(gr + 1) * D + bcol + tx * 4) =
                make_float4(hi[0], hi[1], hi[2], hi[3]);
    }
}

// ---------------- pull aggregate (warp/node, MLP=4) + fused stats (frozen) ----
__global__ __launch_bounds__(256) void k_agg() {
    const int lane = threadIdx.x & 31;
    const int warp0 = (blockIdx.x * blockDim.x + threadIdx.x) >> 5;
    const int nwarps = gridDim.x * (blockDim.x >> 5);

    float s[4]  = {0.f, 0.f, 0.f, 0.f};
    float ss[4] = {0.f, 0.f, 0.f, 0.f};

    for (int v = warp0; v < N_NODES; v += nwarps) {
        float dv = g_dinv[v];
        float4 acc = reinterpret_cast<const float4*>(g_xw + (size_t)v * D)[lane];
        acc.x *= dv; acc.y *= dv; acc.z *= dv; acc.w *= dv;

        int e = g_off[v];
        const int e1 = g_off[v + 1];

        for (; e + 4 <= e1; e += 4) {
            int u0 = g_src[e + 0], u1 = g_src[e + 1];
            int u2 = g_src[e + 2], u3 = g_src[e + 3];
            float d0 = g_dinv[u0], d1 = g_dinv[u1];
            float d2 = g_dinv[u2], d3 = g_dinv[u3];
            float4 x0 = reinterpret_cast<const float4*>(g_xw + (size_t)u0 * D)[lane];
            float4 x1 = reinterpret_cast<const float4*>(g_xw + (size_t)u1 * D)[lane];
            float4 x2 = reinterpret_cast<const float4*>(g_xw + (size_t)u2 * D)[lane];
            float4 x3 = reinterpret_cast<const float4*>(g_xw + (size_t)u3 * D)[lane];
            acc.x = fmaf(d0, x0.x, fmaf(d1, x1.x, fmaf(d2, x2.x, fmaf(d3, x3.x, acc.x))));
            acc.y = fmaf(d0, x0.y, fmaf(d1, x1.y, fmaf(d2, x2.y, fmaf(d3, x3.y, acc.y))));
            acc.z = fmaf(d0, x0.z, fmaf(d1, x1.z, fmaf(d2, x2.z, fmaf(d3, x3.z, acc.z))));
            acc.w = fmaf(d0, x0.w, fmaf(d1, x1.w, fmaf(d2, x2.w, fmaf(d3, x3.w, acc.w))));
        }
        for (; e < e1; e++) {
            int u = g_src[e];
            float du = g_dinv[u];
            float4 xu = reinterpret_cast<const float4*>(g_xw + (size_t)u * D)[lane];
            acc.x = fmaf(du, xu.x, acc.x);
            acc.y = fmaf(du, xu.y, acc.y);
            acc.z = fmaf(du, xu.z, acc.z);
            acc.w = fmaf(du, xu.w, acc.w);
        }

        acc.x *= dv; acc.y *= dv; acc.z *= dv; acc.w *= dv;
        reinterpret_cast<float4*>(g_agg + (size_t)v * D)[lane] = acc;

        s[0] += acc.x; s[1] += acc.y; s[2] += acc.z; s[3] += acc.w;
        ss[0] += acc.x * acc.x; ss[1] += acc.y * acc.y;
        ss[2] += acc.z * acc.z; ss[3] += acc.w * acc.w;
    }

    __shared__ float sm_s[D], sm_ss[D];
    if (threadIdx.x < D) { sm_s[threadIdx.x] = 0.f; sm_ss[threadIdx.x] = 0.f; }
    __syncthreads();
#pragma unroll
    for (int q = 0; q < 4; q++) {
        atomicAdd(&sm_s[lane * 4 + q], s[q]);
        atomicAdd(&sm_ss[lane * 4 + q], ss[q]);
    }
    __syncthreads();
    if (threadIdx.x < D) {
        atomicAdd(&g_colsum[threadIdx.x], sm_s[threadIdx.x]);
        atomicAdd(&g_colss[threadIdx.x],  sm_ss[threadIdx.x]);
    }
}

// ---------------- output: fused finalize + normalize + relu + residual --------
__global__ __launch_bounds__(256) void k_output(float* __restrict__ out) {
    __shared__ float s_mean[D];
    __shared__ float red[D];
    __shared__ float s_scale;
    const int t = threadIdx.x;

    // per-block redundant finalize (cheap: 2*128 L2-hot loads + log reduction)
    if (t < D) {
        float m = g_colsum[t] * (1.0f / N_NODES);
        s_mean[t] = m;
        red[t] = g_colss[t] - (float)N_NODES * m * m;   // sum (v-m)^2 for col t
    }
    __syncthreads();
    for (int off = D / 2; off > 0; off >>= 1) {
        if (t < off) red[t] += red[t + off];
        __syncthreads();
    }
    if (t == 0) s_scale = rsqrtf(EPS + red[0] * (1.0f / N_NODES));
    __syncthreads();
    const float scale = s_scale;

    const int n4 = N_NODES * D / 4;
    const int stride = gridDim.x * blockDim.x;
    for (int idx = blockIdx.x * blockDim.x + t; idx < n4; idx += stride) {
        const int c = (idx & (D / 4 - 1)) * 4;
        float4 v = reinterpret_cast<const float4*>(g_agg)[idx];
        float o0 = (v.x - s_mean[c + 0]) * scale;
        float o1 = (v.y - s_mean[c + 1]) * scale;
        float o2 = (v.z - s_mean[c + 2]) * scale;
        float o3 = (v.w - s_mean[c + 3]) * scale;
        float4 y;
        y.x = fmaxf(o0, 0.f) + o0;
        y.y = fmaxf(o1, 0.f) + o1;
        y.z = fmaxf(o2, 0.f) + o2;
        y.w = fmaxf(o3, 0.f) + o3;
        reinterpret_cast<float4*>(out)[idx] = y;
    }
}

// ---------------- launch -------------------------------------------------------
extern "C" void kernel_launch(void* const* d_in, const int* in_sizes, int n_in,
                              void* d_out, int out_size) {
    const float* x  = nullptr;
    const float* Wm = nullptr;
    const void*  ei = nullptr;
    for (int i = 0; i < n_in; i++) {
        if (in_sizes[i] == N_NODES * D)           x  = (const float*)d_in[i];
        else if (in_sizes[i] == D * D)            Wm = (const float*)d_in[i];
        else if (in_sizes[i] == 2 * N_EDGES ||
                 in_sizes[i] == 4 * N_EDGES)      ei = d_in[i];
    }
    if (!x)  x  = (const float*)d_in[0];
    if (!Wm) Wm = (const float*)d_in[1];
    if (!ei) ei = d_in[2];
    float* out = (float*)d_out;

    // Fork a second captured stream so the CSR build overlaps the GEMM.
    // Streams/events are intentionally NOT destroyed: they participate in the
    // harness's active graph capture (destroying them would invalidate it).
    // Host-side handles only — no device memory. Falls back to fully serial
    // stream-0 execution (identical work) if any creation fails.
    cudaStream_t s1 = 0;
    cudaEvent_t ev_fork = nullptr, ev_join = nullptr;
    bool forked = false;
    if (cudaStreamCreateWithFlags(&s1, cudaStreamNonBlocking) == cudaSuccess) {
        if (cudaEventCreateWithFlags(&ev_fork, cudaEventDisableTiming) == cudaSuccess &&
            cudaEventCreateWithFlags(&ev_join, cudaEventDisableTiming) == cudaSuccess) {
            forked = true;
        } else {
            s1 = 0;
        }
    } else {
        s1 = 0;
    }

    if (forked) {
        cudaEventRecord(ev_fork, 0);
        cudaStreamWaitEvent(s1, ev_fork, 0);
    }

    // CSR-build chain (independent of GEMM) on s1
    k_zero<<<196, 256, 0, s1>>>((const int*)ei);
    k_degree<<<(N_EDGES + 255) / 256, 256, 0, s1>>>(ei);
    k_scan1<<<SCAN_NBLK, SCAN_B, 0, s1>>>();
    k_scan3<<<SCAN_NBLK, SCAN_B, 0, s1>>>();
    k_fill<<<(N_EDGES + 255) / 256, 256, 0, s1>>>(ei);

    // GEMM on the main (captured) stream — runs concurrently with the chain
    dim3 ggrid((N_NODES + GM - 1) / GM, D / GN);
    k_gemm<<<ggrid, 256>>>(x, Wm);

    if (forked) {
        cudaEventRecord(ev_join, s1);
        cudaStreamWaitEvent(0, ev_join, 0);
    }

    // Aggregate needs both g_xw (main stream) and CSR (s1, joined above)
    k_agg<<<1184, 256>>>();
    k_output<<<1184, 256>>>(out);   // finalize fused into output
}